// round 17
// baseline (speedup 1.0000x reference)
#include <cuda_runtime.h>
#include <cstdint>

#define B_   8
#define T_   512
#define H_   768
#define L_   12
#define FF_  3072
#define BT_  (B_*T_)
#define EPS_ 1e-5f

#define H2_  (H_*H_)
#define HFF_ (H_*FF_)
#define WL_  (5*H2_ + 2*HFF_)
#define WTOT_ ((size_t)L_*WL_ + H2_)

// element offsets of weight families inside a layer block
#define OWK_ 0
#define OWV_ (1*H2_)
#define OWR_ (2*H2_)
#define OWO_ (3*H2_)
#define OFR_ (4*H2_)
#define OFK_ (5*H2_)
#define OFV_ (5*H2_ + HFF_)

// per-layer scale-block layout (floats)
#define SSWK_ 0
#define SSWV_ 768
#define SSWR_ 1536
#define SSWO_ 2304
#define SSFR_ 3072
#define SSFK_ 3840
#define SSFV_ 6912
#define SL_   7680
#define HB_   (L_*SL_)
#define QMAX_ 16256.f

// ---------------- scratch (static device globals; no allocation) ----------
__device__ float g_h[BT_*H_];
__device__ float g_k[BT_*H_];
__device__ float g_v[BT_*H_];
__device__ float g_r[BT_*H_];
__device__ float g_attf[BT_*H_];
__device__ float g_kff[(size_t)BT_*FF_];

// packed int8 hi/lo operand buffers (2 B per element)
// A blocks: 128 rows x 64 k, hi 8KB @0 + lo 8KB @8192 = 16KB
// W blocks:  96 rows x 64 k, hi 6KB @0 + lo 6KB @6144 = 12KB
__device__ __align__(1024) char g_wp [WTOT_*2];
__device__ __align__(1024) char g_xkp[(size_t)BT_*H_*2];
__device__ __align__(1024) char g_xvp[(size_t)BT_*H_*2];
__device__ __align__(1024) char g_xrp[(size_t)BT_*H_*2];
__device__ __align__(1024) char g_atp[(size_t)BT_*H_*2];
__device__ __align__(1024) char g_kfp[(size_t)BT_*FF_*2];

// row scales (stored as rowmax/16256)
__device__ float g_sxk[BT_], g_sxv[BT_], g_sxr[BT_], g_sat[BT_], g_skf[BT_];
// weight column scales
__device__ float g_wsc[HB_ + 768];

// ---------------- helpers ---------------------------------------------------
__device__ __forceinline__ float bsum256(float val, float* red) {
    int lane = threadIdx.x & 31;
    int w    = threadIdx.x >> 5;
#pragma unroll
    for (int o = 16; o; o >>= 1) val += __shfl_xor_sync(0xffffffffu, val, o);
    __syncthreads();
    if (lane == 0) red[w] = val;
    __syncthreads();
    float s = 0.f;
#pragma unroll
    for (int i = 0; i < 8; i++) s += red[i];
    return s;
}

__device__ __forceinline__ float bmax256(float val, float* red) {
    int lane = threadIdx.x & 31;
    int w    = threadIdx.x >> 5;
#pragma unroll
    for (int o = 16; o; o >>= 1) val = fmaxf(val, __shfl_xor_sync(0xffffffffu, val, o));
    __syncthreads();
    if (lane == 0) red[w] = val;
    __syncthreads();
    float s = red[0];
#pragma unroll
    for (int i = 1; i < 8; i++) s = fmaxf(s, red[i]);
    return s;
}

// swizzled 16B-chunk offset within a tile (row, kg of 16 int8)
__device__ __forceinline__ uint32_t goff(int row, int kg) {
    int p = row >> 1;
    int c = (kg ^ (p & 3)) | ((row & 1) << 2);
    return (uint32_t)((p * 8 + c) * 16);
}

// byte offset of int8 element (m, k) in a packed A buffer (hi; lo at +8192)
__device__ __forceinline__ size_t packA8(int m, int k, int K) {
    return ((size_t)(m >> 7) * (K >> 6) + (k >> 6)) * 16384
         + goff(m & 127, (k >> 4) & 3) + (k & 15);
}
// byte offset in packed W buffer (hi; lo at +6144)
__device__ __forceinline__ size_t packW8(int n, int k, int K) {
    return ((size_t)(n / 96) * (K >> 6) + (k >> 6)) * 12288
         + goff(n % 96, (k >> 4) & 3) + (k & 15);
}

// quantize x against scale s (= max/16256): returns qh, ql
__device__ __forceinline__ void q15(float x, float sinv, int8_t& qh, int8_t& ql) {
    int iq = __float2int_rn(x * sinv);
    iq = max(-16256, min(16256, iq));
    int h = (iq + 64) >> 7;
    qh = (int8_t)h;
    ql = (int8_t)(iq - (h << 7));
}

// ---------------- weight column max ------------------------------------------
__global__ void wmax_hh(const float* __restrict__ p0, const float* __restrict__ p1,
                        const float* __restrict__ p2, const float* __restrict__ p3,
                        const float* __restrict__ p4, float* __restrict__ wsc) {
    int z = blockIdx.z;
    int type = z / L_, layer = z % L_;
    const float* src = ((type == 0) ? p0 : (type == 1) ? p1 : (type == 2) ? p2
                      : (type == 3) ? p3 : p4) + (size_t)layer * H2_;
    int fam = (type == 0) ? SSWK_ : (type == 1) ? SSWV_ : (type == 2) ? SSWR_
            : (type == 3) ? SSWO_ : SSFR_;
    int c = blockIdx.x * 256 + threadIdx.x;
    float m = 0.f;
    for (int k = 0; k < H_; k++) m = fmaxf(m, fabsf(src[(size_t)k * H_ + c]));
    wsc[(size_t)layer * SL_ + fam + c] = fmaxf(m, 1e-30f) / QMAX_;
}

__global__ void wmax_rect(const float* __restrict__ p, float* __restrict__ sc,
                          int Kd, int Nd, int scStride) {
    int layer = blockIdx.z;
    const float* src = p + (size_t)layer * Kd * Nd;
    int c = blockIdx.x * 256 + threadIdx.x;
    float m = 0.f;
    for (int k = 0; k < Kd; k++) m = fmaxf(m, fabsf(src[(size_t)k * Nd + c]));
    sc[(size_t)layer * scStride + c] = fmaxf(m, 1e-30f) / QMAX_;
}

// ---------------- weight transpose + quantize -> packed W blocks -------------
__device__ __forceinline__ void transT_body(const float* __restrict__ in,
                                            char* __restrict__ op,
                                            const float* __restrict__ wsc,
                                            int Kd, int Nd) {
    __shared__ float t[32][33];
    int n0 = blockIdx.x * 32, k0 = blockIdx.y * 32;
    int tx = threadIdx.x, ty = threadIdx.y;   // 32 x 8
#pragma unroll
    for (int i = 0; i < 32; i += 8)
        t[ty + i][tx] = in[(size_t)(k0 + ty + i) * Nd + n0 + tx];
    __syncthreads();
#pragma unroll
    for (int i = 0; i < 32; i += 8) {
        int n = n0 + ty + i;
        int k = k0 + tx;
        float sinv = 1.f / (wsc[n] * QMAX_) * QMAX_;   // = 1/wsc[n] ... keep simple
        sinv = 1.f / wsc[n];
        float x = t[tx][ty + i];
        int8_t qh, ql; q15(x * (1.f / QMAX_) * QMAX_, sinv / QMAX_ * QMAX_, qh, ql);
        // simpler: iq = rn(x / wsc[n])... wsc = max/16256 so x/wsc in [-16256,16256]
        {
            int iq = __float2int_rn(x * sinv);
            iq = max(-16256, min(16256, iq));
            int hh = (iq + 64) >> 7;
            qh = (int8_t)hh; ql = (int8_t)(iq - (hh << 7));
        }
        size_t off = packW8(n, k, Kd);
        *(int8_t*)(op + off)        = qh;
        *(int8_t*)(op + off + 6144) = ql;
    }
}

__global__ void transT(const float* __restrict__ in, char* __restrict__ op,
                       const float* __restrict__ wsc, int Kd, int Nd) {
    transT_body(in, op, wsc, Kd, Nd);
}

__global__ void transT_hh(const float* __restrict__ p0, const float* __restrict__ p1,
                          const float* __restrict__ p2, const float* __restrict__ p3,
                          const float* __restrict__ p4, char* __restrict__ wp,
                          const float* __restrict__ wsc) {
    int z = blockIdx.z;
    int type = z / L_, layer = z % L_;
    const float* src = (type == 0) ? p0 : (type == 1) ? p1 : (type == 2) ? p2
                     : (type == 3) ? p3 : p4;
    size_t ooff = ((size_t)layer * WL_ +
        ((type == 0) ? OWK_ : (type == 1) ? OWV_ : (type == 2) ? OWR_
       : (type == 3) ? OWO_ : OFR_)) * 2;
    int fam = (type == 0) ? SSWK_ : (type == 1) ? SSWV_ : (type == 2) ? SSWR_
            : (type == 3) ? SSWO_ : SSFR_;
    transT_body(src + (size_t)layer * H2_, wp + ooff,
                wsc + (size_t)layer * SL_ + fam, H_, H_);
}

__global__ void transT_rect(const float* __restrict__ p, char* __restrict__ wp,
                            const float* __restrict__ wsc,
                            int Kd, int Nd, size_t ooff_elem, int scOff) {
    int layer = blockIdx.z;
    size_t o = ((size_t)layer * WL_ + ooff_elem) * 2;
    transT_body(p + (size_t)layer * Kd * Nd, wp + o,
                wsc + (size_t)layer * SL_ + scOff, Kd, Nd);
}

// ---------------- LayerNorms -------------------------------------------------
__global__ void ln_kernel(const float* __restrict__ in,
                          const float* __restrict__ w,
                          const float* __restrict__ b,
                          float* __restrict__ out) {
    __shared__ float red[8];
    size_t base = (size_t)blockIdx.x * H_;
    float c[3];
    float s = 0.f, s2 = 0.f;
#pragma unroll
    for (int i = 0; i < 3; i++) {
        int j = threadIdx.x + i * 256;
        c[i] = in[base + j];
        s += c[i]; s2 += c[i] * c[i];
    }
    s  = bsum256(s,  red);
    s2 = bsum256(s2, red);
    float m = s / H_, v = s2 / H_ - m * m, rs = rsqrtf(v + EPS_);
#pragma unroll
    for (int i = 0; i < 3; i++) {
        int j = threadIdx.x + i * 256;
        out[base + j] = (c[i] - m) * rs * w[j] + b[j];
    }
}

__global__ void ln_quant(const float* __restrict__ in,
                         const float* __restrict__ w,
                         const float* __restrict__ b,
                         char* __restrict__ op, float* __restrict__ srow) {
    __shared__ float red[8];
    int row = blockIdx.x;
    size_t base = (size_t)row * H_;
    float c[3];
    float s = 0.f, s2 = 0.f;
#pragma unroll
    for (int i = 0; i < 3; i++) {
        int j = threadIdx.x + i * 256;
        c[i] = in[base + j];
        s += c[i]; s2 += c[i] * c[i];
    }
    s  = bsum256(s,  red);
    s2 = bsum256(s2, red);
    float m = s / H_, v = s2 / H_ - m * m, rs = rsqrtf(v + EPS_);
    float x[3], mx = 0.f;
#pragma unroll
    for (int i = 0; i < 3; i++) {
        int j = threadIdx.x + i * 256;
        x[i] = (c[i] - m) * rs * w[j] + b[j];
        mx = fmaxf(mx, fabsf(x[i]));
    }
    mx = bmax256(mx, red);
    mx = fmaxf(mx, 1e-30f);
    float sinv = QMAX_ / mx;
    if (threadIdx.x == 0) srow[row] = mx / QMAX_;
#pragma unroll
    for (int i = 0; i < 3; i++) {
        int j = threadIdx.x + i * 256;
        int8_t qh, ql; q15(x[i], sinv, qh, ql);
        size_t off = packA8(row, j, H_);
        *(int8_t*)(op + off)        = qh;
        *(int8_t*)(op + off + 8192) = ql;
    }
}

// ---------------- LN + token-shift + lerp-mix -> quantized packed -------------
__global__ void prep_mix(const float* __restrict__ hbuf,
                         const float* __restrict__ lnw, const float* __restrict__ lnb,
                         const float* __restrict__ mk,  const float* __restrict__ mv,
                         const float* __restrict__ mr,
                         char* __restrict__ xkp, char* __restrict__ xvp,
                         char* __restrict__ xrp,
                         float* __restrict__ sxk, float* __restrict__ sxv,
                         float* __restrict__ sxr) {
    __shared__ float red[8];
    int row = blockIdx.x;
    int t   = row % T_;
    const float* cur = hbuf + (size_t)row * H_;
    float c[3], p[3];
    float sc = 0.f, sc2 = 0.f, sp = 0.f, sp2 = 0.f;
#pragma unroll
    for (int i = 0; i < 3; i++) {
        int j = threadIdx.x + i * 256;
        c[i] = cur[j];
        sc += c[i]; sc2 += c[i] * c[i];
        p[i] = (t > 0) ? cur[j - H_] : 0.f;
        sp += p[i]; sp2 += p[i] * p[i];
    }
    sc  = bsum256(sc,  red);
    sc2 = bsum256(sc2, red);
    sp  = bsum256(sp,  red);
    sp2 = bsum256(sp2, red);
    float mc = sc / H_, vc = sc2 / H_ - mc * mc, rc = rsqrtf(vc + EPS_);
    float mp = sp / H_, vp = sp2 / H_ - mp * mp, rp = rsqrtf(vp + EPS_);

    float vk[3], vv[3], vr[3];
    float mk_ = 0.f, mv_ = 0.f, mr_ = 0.f;
#pragma unroll
    for (int i = 0; i < 3; i++) {
        int j = threadIdx.x + i * 256;
        float w = lnw[j], bb = lnb[j];
        float hn = (c[i] - mc) * rc * w + bb;
        float sh = (t > 0) ? ((p[i] - mp) * rp * w + bb) : 0.f;
        float k_ = mk[j];
        vk[i] = hn * k_ + sh * (1.f - k_);
        mk_ = fmaxf(mk_, fabsf(vk[i]));
        if (xvp) {
            float v_ = mv[j];
            vv[i] = hn * v_ + sh * (1.f - v_);
            mv_ = fmaxf(mv_, fabsf(vv[i]));
        }
        float r_ = mr[j];
        vr[i] = hn * r_ + sh * (1.f - r_);
        mr_ = fmaxf(mr_, fabsf(vr[i]));
    }
    mk_ = fmaxf(bmax256(mk_, red), 1e-30f);
    if (xvp) mv_ = fmaxf(bmax256(mv_, red), 1e-30f);
    mr_ = fmaxf(bmax256(mr_, red), 1e-30f);
    if (threadIdx.x == 0) {
        sxk[row] = mk_ / QMAX_;
        if (xvp) sxv[row] = mv_ / QMAX_;
        sxr[row] = mr_ / QMAX_;
    }
    float ik = QMAX_ / mk_, iv = QMAX_ / mv_, ir = QMAX_ / mr_;
#pragma unroll
    for (int i = 0; i < 3; i++) {
        int j = threadIdx.x + i * 256;
        size_t off = packA8(row, j, H_);
        int8_t qh, ql;
        q15(vk[i], ik, qh, ql);
        *(int8_t*)(xkp + off) = qh; *(int8_t*)(xkp + off + 8192) = ql;
        if (xvp) {
            q15(vv[i], iv, qh, ql);
            *(int8_t*)(xvp + off) = qh; *(int8_t*)(xvp + off + 8192) = ql;
        }
        q15(vr[i], ir, qh, ql);
        *(int8_t*)(xrp + off) = qh; *(int8_t*)(xrp + off + 8192) = ql;
    }
}

// ---------------- generic row quantizer (fp32 [rows][N] -> packed + scale) ---
template <int N>
__global__ void quant_rows(const float* __restrict__ in, char* __restrict__ op,
                           float* __restrict__ srow) {
    __shared__ float red[8];
    int row = blockIdx.x;
    const float* src = in + (size_t)row * N;
    const int E = N / 256;
    float x[E], mx = 0.f;
#pragma unroll
    for (int i = 0; i < E; i++) {
        x[i] = src[threadIdx.x + i * 256];
        mx = fmaxf(mx, fabsf(x[i]));
    }
    mx = fmaxf(bmax256(mx, red), 1e-30f);
    if (threadIdx.x == 0) srow[row] = mx / QMAX_;
    float sinv = QMAX_ / mx;
#pragma unroll
    for (int i = 0; i < E; i++) {
        int j = threadIdx.x + i * 256;
        int8_t qh, ql; q15(x[i], sinv, qh, ql);
        size_t off = packA8(row, j, N);
        *(int8_t*)(op + off)        = qh;
        *(int8_t*)(op + off + 8192) = ql;
    }
}

// ---------------- WKV scan (fp32 out, fused r-gate, pipelined) ----------------
#define WG_ 16
__global__ void wkv_kernel(const float* __restrict__ k,
                           const float* __restrict__ v,
                           const float* __restrict__ r,
                           const float* __restrict__ td,
                           const float* __restrict__ tf,
                           float* __restrict__ att) {
    int c = blockIdx.x * blockDim.x + threadIdx.x;
    if (c >= B_ * H_) return;
    int b = c / H_, hh = c % H_;
    float w = -expf(td[hh]);
    float u = tf[hh];
    float num = 0.f, den = 0.f, mx = -1e38f;
    size_t base = (size_t)b * T_ * H_ + hh;

    float ka[WG_], va[WG_], ra[WG_];
    float kb[WG_], vb[WG_], rb[WG_];

    auto stage = [&](float (&kq)[WG_], float (&vq)[WG_], float (&rq)[WG_], int g) {
#pragma unroll
        for (int j = 0; j < WG_; j++) {
            size_t i = base + (size_t)(g * WG_ + j) * H_;
            kq[j] = k[i]; vq[j] = v[i]; rq[j] = r[i];
        }
    };
    auto work = [&](float (&kq)[WG_], float (&vq)[WG_], float (&rq)[WG_], int g) {
#pragma unroll
        for (int j = 0; j < WG_; j++) {
            size_t idx = base + (size_t)(g * WG_ + j) * H_;
            float kt_ = kq[j], vt = vq[j];
            float a  = kt_ + u;
            float mo = fmaxf(mx, a);
            float e1 = expf(mx - mo), e2 = expf(a - mo);
            att[idx] = ((e1 * num + e2 * vt) / (e1 * den + e2)) * rq[j];
            float ms = fmaxf(mx + w, kt_);
            float f1 = expf(mx + w - ms), f2 = expf(kt_ - ms);
            num = f1 * num + f2 * vt;
            den = f1 * den + f2;
            mx  = ms;
        }
    };

    const int NG = T_ / WG_;
    stage(ka, va, ra, 0);
#pragma unroll 1
    for (int g = 0; g < NG; g += 2) {
        if (g + 1 < NG) stage(kb, vb, rb, g + 1);
        work(ka, va, ra, g);
        if (g + 2 < NG) stage(ka, va, ra, g + 2);
        if (g + 1 < NG) work(kb, vb, rb, g + 1);
    }
}

// ====================== int8 2-level tensor-core GEMM ========================
// Tile 128x96, 384 threads = 12 warps (2x6), warp tile 64x16, K-tile 64.
// 4-stage cp.async.bulk pipeline (proven R13 skeleton).
// Passes per k32 step: qh*qh -> accA; ql*qh -> accB; qh*ql -> accB.
// v = sa[r]*sw[c]*(16384*accA + 128*accB)
// epi: 0 C=v, 1 C=sigmoid(v), 2 C+=v, 3 C+=aux*v, 4 C=relu(v)^2

#define TN_     96
#define AL_OFF  8192
#define BH_OFF  16384
#define BL_OFF  22528
#define STG_B   28672
#define NSTG    4
#define GEMM_SMEM (NSTG*STG_B)
#define GT_     384

__device__ __forceinline__ void mbar_init(uint32_t a, uint32_t cnt) {
    asm volatile("mbarrier.init.shared.b64 [%0], %1;" :: "r"(a), "r"(cnt) : "memory");
}
__device__ __forceinline__ void mbar_wait(uint32_t a, uint32_t parity) {
    asm volatile(
        "{ .reg .pred P;\n"
        "WL_%=: mbarrier.try_wait.parity.acquire.cta.shared::cta.b64 P, [%0], %1, 0x989680;\n"
        "@P bra WD_%=;\n"
        "bra WL_%=;\n"
        "WD_%=: }\n" :: "r"(a), "r"(parity) : "memory");
}
__device__ __forceinline__ void mbar_expect_tx(uint32_t a, uint32_t bytes) {
    asm volatile("mbarrier.arrive.expect_tx.shared.b64 _, [%0], %1;"
                 :: "r"(a), "r"(bytes) : "memory");
}
__device__ __forceinline__ void bulk_g2s(uint32_t dst, const void* src,
                                         uint32_t bytes, uint32_t mbar) {
    asm volatile(
        "cp.async.bulk.shared::cta.global.mbarrier::complete_tx::bytes [%0], [%1], %2, [%3];"
        :: "r"(dst), "l"(src), "r"(bytes), "r"(mbar) : "memory");
}
__device__ __forceinline__ void ldsm4(uint32_t r[4], uint32_t a) {
    asm volatile("ldmatrix.sync.aligned.m8n8.x4.shared.b16 {%0,%1,%2,%3}, [%4];\n"
                 : "=r"(r[0]), "=r"(r[1]), "=r"(r[2]), "=r"(r[3]) : "r"(a));
}
__device__ __forceinline__ void imma(int c[4], const uint32_t a[4],
                                     uint32_t b0, uint32_t b1) {
    asm volatile(
        "mma.sync.aligned.m16n8k32.row.col.s32.s8.s8.s32 "
        "{%0,%1,%2,%3}, {%4,%5,%6,%7}, {%8,%9}, {%0,%1,%2,%3};\n"
        : "+r"(c[0]), "+r"(c[1]), "+r"(c[2]), "+r"(c[3])
        : "r"(a[0]), "r"(a[1]), "r"(a[2]), "r"(a[3]), "r"(b0), "r"(b1));
}

__device__ __forceinline__ void tc_body(
    const char* __restrict__ Ap, const float* __restrict__ sa,
    const char* __restrict__ Bp, const float* __restrict__ sw,
    float* __restrict__ C, const float* __restrict__ aux,
    int epi, int N, int K, int bm, int bnt, uint8_t* sm8) {

    __shared__ uint64_t s_mb[NSTG];
    uint32_t sb = (uint32_t)__cvta_generic_to_shared(sm8);
    uint32_t mb = (uint32_t)__cvta_generic_to_shared(&s_mb[0]);

    int tid = threadIdx.x;
    int l   = tid & 31;
    int w   = tid >> 5;        // 0..11
    int wm  = w / 6;           // 0..1
    int wn  = w % 6;           // 0..5
    int sub = l >> 3;
    int bn  = bnt * TN_;
    int nkt = K >> 6;

    if (tid == 0) {
#pragma unroll
        for (int s = 0; s < NSTG; s++) mbar_init(mb + 8*s, 1);
    }
    __syncthreads();

    auto issue = [&](int i) {
        int s = i & (NSTG - 1);
        uint32_t st = sb + s * STG_B;
        mbar_expect_tx(mb + 8*s, STG_B);
        size_t ab = ((size_t)(bm >> 7) * nkt + i) * 16384;
        size_t bb = ((size_t)bnt * nkt + i) * 12288;
        bulk_g2s(st,          Ap + ab, 16384, mb + 8*s);
        bulk_g2s(st + BH_OFF, Bp + bb, 12288, mb + 8*s);
    };
    if (tid == 0) { issue(0); issue(1); issue(2); issue(3); }

    int accA[4][2][4], accB[4][2][4];
#pragma unroll
    for (int mi = 0; mi < 4; mi++)
#pragma unroll
        for (int ni = 0; ni < 2; ni++)
#pragma unroll
            for (int q = 0; q < 4; q++) { accA[mi][ni][q] = 0; accB[mi][ni][q] = 0; }

    int arow0 = wm * 64 + (l & 7) + ((sub & 1) << 3);
    int brow0 = wn * 16 + (l & 7) + ((sub >> 1) << 3);
    int akg_  = (sub >> 1);
    int bkg_  = (sub & 1);

#pragma unroll 1
    for (int i = 0; i < nkt; i++) {
        int s = i & (NSTG - 1);
        mbar_wait(mb + 8*s, (i >> 2) & 1);
        uint32_t st = sb + s * STG_B;

#pragma unroll
        for (int ks = 0; ks < 2; ks++) {
            int akg = ks * 2 + akg_;
            int bkg = ks * 2 + bkg_;

            uint32_t ah[4][4], bh[4], al[4][4], bl[4];
#pragma unroll
            for (int mi = 0; mi < 4; mi++) ldsm4(ah[mi], st + goff(arow0 + mi * 16, akg));
            ldsm4(bh, st + BH_OFF + goff(brow0, bkg));

            // pass 1: qh*qh -> accA
#pragma unroll
            for (int mi = 0; mi < 4; mi++) {
                imma(accA[mi][0], ah[mi], bh[0], bh[1]);
                imma(accA[mi][1], ah[mi], bh[2], bh[3]);
            }
            // pass 2: ql*qh -> accB
#pragma unroll
            for (int mi = 0; mi < 4; mi++) ldsm4(al[mi], st + AL_OFF + goff(arow0 + mi * 16, akg));
#pragma unroll
            for (int mi = 0; mi < 4; mi++) {
                imma(accB[mi][0], al[mi], bh[0], bh[1]);
                imma(accB[mi][1], al[mi], bh[2], bh[3]);
            }
            // pass 3: qh*ql -> accB
            ldsm4(bl, st + BL_OFF + goff(brow0, bkg));
#pragma unroll
            for (int mi = 0; mi < 4; mi++) {
                imma(accB[mi][0], ah[mi], bl[0], bl[1]);
                imma(accB[mi][1], ah[mi], bl[2], bl[3]);
            }
        }

        __syncthreads();
        if (tid == 0 && i + NSTG < nkt) issue(i + NSTG);
    }

    // ---- epilogue ----
#pragma unroll
    for (int mi = 0; mi < 4; mi++) {
#pragma unroll
        for (int ni = 0; ni < 2; ni++) {
            int r0 = bm + wm * 64 + mi * 16 + (l >> 2);
            int c0 = bn + wn * 16 + ni * 8 + (l & 3) * 2;
#pragma unroll
            for (int q = 0; q < 4; q++) {
                int rr = r0 + (q >> 1) * 8;
                int cc = c0 + (q & 1);
                float v = sa[rr] * sw[cc] *
                          (16384.f * (float)accA[mi][ni][q] + 128.f * (float)accB[mi][ni][q]);
                size_t idx = (size_t)rr * N + cc;
                if (epi == 0)      C[idx] = v;
                else if (epi == 1) C[idx] = 1.f / (1.f + expf(-v));
                else if (epi == 2) C[idx] += v;
                else if (epi == 3) C[idx] += aux[idx] * v;
                else {             float rq2 = fmaxf(v, 0.f); C[idx] = rq2 * rq2; }
            }
        }
    }
}

// ---- kernel wrappers ----
__global__ __launch_bounds__(GT_, 1) void tgemm(
    const char* __restrict__ Ap, const float* __restrict__ sa,
    const char* __restrict__ Bp, const float* __restrict__ sw,
    float* C, const float* aux, int epi, int N, int K) {
    extern __shared__ __align__(16) uint8_t sm8[];
    tc_body(Ap, sa, Bp, sw, C, aux, epi, N, K, blockIdx.y * 128, blockIdx.x, sm8);
}

// batched k/v/r: grid (8, 32, 3)
__global__ __launch_bounds__(GT_, 1) void tgemm_kvr(const char* __restrict__ wp,
                                                    const float* __restrict__ wsc) {
    extern __shared__ __align__(16) uint8_t sm8[];
    int z = blockIdx.z;
    const char*  Ap = (z == 0) ? g_xkp : (z == 1) ? g_xvp : g_xrp;
    const float* sa = (z == 0) ? g_sxk : (z == 1) ? g_sxv : g_sxr;
    size_t wo = ((z == 0) ? (size_t)OWK_ : (z == 1) ? (size_t)OWV_ : (size_t)OWR_) * 2;
    const float* sw = wsc + ((z == 0) ? SSWK_ : (z == 1) ? SSWV_ : SSWR_);
    float* C = (z == 0) ? g_k : (z == 1) ? g_v : g_r;
    tc_body(Ap, sa, wp + wo, sw, C, nullptr, (z == 2) ? 1 : 0, H_, H_,
            blockIdx.y * 128, blockIdx.x, sm8);
}

// batched Fk (x<32) + Fr (x>=32): grid (40, 32)
__global__ __launch_bounds__(GT_, 1) void tgemm_ff(const char* __restrict__ wp,
                                                   const float* __restrict__ wsc) {
    extern __shared__ __align__(16) uint8_t sm8[];
    int bx = blockIdx.x;
    if (bx < 32)
        tc_body(g_xkp, g_sxk, wp + (size_t)OFK_ * 2, wsc + SSFK_, g_kff, nullptr,
                4, FF_, H_, blockIdx.y * 128, bx, sm8);
    else
        tc_body(g_xrp, g_sxr, wp + (size_t)OFR_ * 2, wsc + SSFR_, g_r, nullptr,
                1, H_, H_, blockIdx.y * 128, bx - 32, sm8);
}

// ---------------- host orchestration -----------------------------------------
extern "C" void kernel_launch(void* const* d_in, const int* in_sizes, int n_in,
                              void* d_out, int out_size) {
    (void)in_sizes; (void)n_in; (void)out_size;
    const float* x     = (const float*)d_in[0];
    const float* prew  = (const float*)d_in[1];
    const float* preb  = (const float*)d_in[2];
    const float* ln1w  = (const float*)d_in[3];
    const float* ln1b  = (const float*)d_in[4];
    const float* ln2w  = (const float*)d_in[5];
    const float* ln2b  = (const float*)d_in[6];
    const float* td    = (const float*)d_in[7];
    const float* tf    = (const float*)d_in[8];
    const float* amk   = (const float*)d_in[9];
    const float* amv   = (const float*)d_in[10];
    const float* amr   = (const float*)d_in[11];
    const float* Wk    = (const float*)d_in[12];
    const float* Wv    = (const float*)d_in[13];
    const float* Wr    = (const float*)d_in[14];
    const float* Wo    = (const float*)d_in[15];
    const float* fmk   = (const float*)d_in[16];
    const float* fmr   = (const float*)d_in[17];
    const float* Fk    = (const float*)d_in[18];
    const float* Fv    = (const float*)d_in[19];
    const float* Fr    = (const float*)d_in[20];
    const float* lnow  = (const float*)d_in[21];
    const float* lnob  = (const float*)d_in[22];
    const float* headw = (const float*)d_in[23];

    float *h, *k, *v, *r, *attf, *kff;
    float *sxk, *sxv, *sxr, *sat, *skf, *wsc;
    char *wp, *xkp, *xvp, *xrp, *atp, *kfp;
    cudaGetSymbolAddress((void**)&h,    g_h);
    cudaGetSymbolAddress((void**)&k,    g_k);
    cudaGetSymbolAddress((void**)&v,    g_v);
    cudaGetSymbolAddress((void**)&r,    g_r);
    cudaGetSymbolAddress((void**)&attf, g_attf);
    cudaGetSymbolAddress((void**)&kff,  g_kff);
    cudaGetSymbolAddress((void**)&wp,   g_wp);
    cudaGetSymbolAddress((void**)&xkp,  g_xkp);
    cudaGetSymbolAddress((void**)&xvp,  g_xvp);
    cudaGetSymbolAddress((void**)&xrp,  g_xrp);
    cudaGetSymbolAddress((void**)&atp,  g_atp);
    cudaGetSymbolAddress((void**)&kfp,  g_kfp);
    cudaGetSymbolAddress((void**)&sxk,  g_sxk);
    cudaGetSymbolAddress((void**)&sxv,  g_sxv);
    cudaGetSymbolAddress((void**)&sxr,  g_sxr);
    cudaGetSymbolAddress((void**)&sat,  g_sat);
    cudaGetSymbolAddress((void**)&skf,  g_skf);
    cudaGetSymbolAddress((void**)&wsc,  g_wsc);

    cudaFuncSetAttribute(tgemm,     cudaFuncAttributeMaxDynamicSharedMemorySize, GEMM_SMEM);
    cudaFuncSetAttribute(tgemm_kvr, cudaFuncAttributeMaxDynamicSharedMemorySize, GEMM_SMEM);
    cudaFuncSetAttribute(tgemm_ff,  cudaFuncAttributeMaxDynamicSharedMemorySize, GEMM_SMEM);

    dim3 blk(256);
    dim3 gblk(GT_);
    dim3 tb(32, 8);
    dim3 gHHz(H_ / 32, H_ / 32, 5 * L_);
    dim3 gHFz(FF_ / 32, H_ / 32, L_);
    dim3 gFHz(H_ / 32, FF_ / 32, L_);
    dim3 gHH(H_ / 32, H_ / 32);
    dim3 gWHH(3, 1, 5 * L_);
    dim3 gWFK(12, 1, L_);
    dim3 gWFV(3, 1, L_);
    dim3 gWHD(3, 1, 1);
    dim3 gH(H_ / TN_,  BT_ / 128);        // (8, 32)
    dim3 gKVR(H_ / TN_, BT_ / 128, 3);    // (8, 32, 3)
    dim3 gFF(FF_ / TN_ + H_ / TN_, BT_ / 128);  // (40, 32)

    // ---- weight scales + transpose/quantize ----
    wmax_hh<<<gWHH, blk>>>(Wk, Wv, Wr, Wo, Fr, wsc);
    wmax_rect<<<gWFK, blk>>>(Fk, wsc + SSFK_, H_, FF_, SL_);
    wmax_rect<<<gWFV, blk>>>(Fv, wsc + SSFV_, FF_, H_, SL_);
    wmax_rect<<<gWHD, blk>>>(headw, wsc + HB_, H_, H_, 0);
    transT_hh<<<gHHz, tb>>>(Wk, Wv, Wr, Wo, Fr, wp, wsc);
    transT_rect<<<gHFz, tb>>>(Fk, wp, wsc, H_, FF_, (size_t)OFK_, SSFK_);
    transT_rect<<<gFHz, tb>>>(Fv, wp, wsc, FF_, H_, (size_t)OFV_, SSFV_);
    size_t hb2 = (size_t)L_ * WL_ * 2;
    transT<<<gHH, tb>>>(headw, wp + hb2, wsc + HB_, H_, H_);

    // ---- block 0 pre-LN ----
    ln_kernel<<<BT_, blk>>>(x, prew, preb, h);

    for (int i = 0; i < L_; i++) {
        size_t oH  = (size_t)i * H_;
        size_t wb2 = (size_t)i * WL_ * 2;
        const float* lsc = wsc + (size_t)i * SL_;

        // --- time mixing ---
        prep_mix<<<BT_, blk>>>(h, ln1w + oH, ln1b + oH, amk + oH, amv + oH, amr + oH,
                               xkp, xvp, xrp, sxk, sxv, sxr);
        tgemm_kvr<<<gKVR, gblk, GEMM_SMEM>>>(wp + wb2, lsc);
        wkv_kernel<<<(B_ * H_ + 255) / 256, blk>>>(k, v, r, td + oH, tf + oH, attf);
        quant_rows<H_><<<BT_, blk>>>(attf, atp, sat);
        tgemm<<<gH, gblk, GEMM_SMEM>>>(atp, sat, wp + wb2 + (size_t)OWO_ * 2,
                                       lsc + SSWO_, h, nullptr, 2, H_, H_);

        // --- channel mixing ---
        prep_mix<<<BT_, blk>>>(h, ln2w + oH, ln2b + oH, fmk + oH, nullptr, fmr + oH,
                               xkp, nullptr, xrp, sxk, nullptr, sxr);
        tgemm_ff<<<gFF, gblk, GEMM_SMEM>>>(wp + wb2, lsc);
        quant_rows<FF_><<<BT_, blk>>>(kff, kfp, skf);
        tgemm<<<gH, gblk, GEMM_SMEM>>>(kfp, skf, wp + wb2 + (size_t)OFV_ * 2,
                                       lsc + SSFV_, h, r, 3, H_, FF_);
    }

    ln_quant<<<BT_, blk>>>(h, lnow, lnob, xkp, sxk);
    tgemm<<<gH, gblk, GEMM_SMEM>>>(xkp, sxk, wp + hb2, wsc + HB_,
                                   (float*)d_out, nullptr, 0, H_, H_);
}